// round 6
// baseline (speedup 1.0000x reference)
#include <cuda_runtime.h>
#include <math.h>

// Problem constants (fixed by the dataset)
#define VOCAB   32000
#define NBL     128        // B*L
#define NK      64         // 8 heads x 8

// Main-kernel tiling: 128 threads, each owns 4 bl-rows x 8 vocab-cols
#define BM      64         // bl tile -> grid.y = 2
#define BN      64         // vocab tile -> grid.x = 500
#define KC      8          // k chunk for bl-coefficient smem
#define NTHR    128

typedef unsigned long long u64;

// ---------------------------------------------------------------------------
// Packed f32x2 helpers
// ---------------------------------------------------------------------------
__device__ __forceinline__ u64 pk(float x, float y) {
    u64 r; asm("mov.b64 %0, {%1, %2};" : "=l"(r) : "f"(x), "f"(y)); return r;
}
__device__ __forceinline__ void upk(u64 a, float& x, float& y) {
    asm("mov.b64 {%0, %1}, %2;" : "=f"(x), "=f"(y) : "l"(a));
}
__device__ __forceinline__ u64 mul2(u64 a, u64 b) {
    u64 r; asm("mul.rn.f32x2 %0, %1, %2;" : "=l"(r) : "l"(a), "l"(b)); return r;
}
__device__ __forceinline__ u64 fma2(u64 a, u64 b, u64 c) {
    u64 r; asm("fma.rn.f32x2 %0, %1, %2, %3;" : "=l"(r) : "l"(a), "l"(b), "l"(c)); return r;
}
__device__ __forceinline__ u64 add2(u64 a, u64 b) {
    u64 r; asm("add.rn.f32x2 %0, %1, %2;" : "=l"(r) : "l"(a), "l"(b)); return r;
}

// ---------------------------------------------------------------------------
// Device scratch: per-(k,bl) coefficients, PRE-DUPLICATED as (x,x) u64 pairs
// ---------------------------------------------------------------------------
__device__ __align__(16) u64 g_cpd[NK * NBL];   // [k][bl] = (cp, cp)
__device__ __align__(16) u64 g_epd[NK * NBL];   // [k][bl] = (e^f, e^f)
__device__ __align__(16) u64 g_emd[NK * NBL];   // [k][bl] = (e^-f, e^-f)

__global__ void prep_bl(const float* __restrict__ freqs,
                        const float* __restrict__ amps,
                        const float* __restrict__ phases,
                        const float* __restrict__ iph,
                        const float* __restrict__ W) {
    int idx = blockIdx.x * 256 + threadIdx.x;   // idx = bl*NK + k
    int bl = idx >> 6, k = idx & 63;
    float cp = amps[idx] * cosf(phases[idx] - iph[k]) * W[k >> 3];
    float f  = freqs[idx];
    float ep = expf(f), em = expf(-f);
    int o = k * NBL + bl;
    g_cpd[o] = pk(cp, cp);
    g_epd[o] = pk(ep, ep);
    g_emd[o] = pk(em, em);
}

// ---------------------------------------------------------------------------
// Main: out[bl][v] = sum_k cp * min(e^f * e^-vp, e^-f * e^vp) + bias
//  - vocab smem: [k][pair p] float4 = (em_2p, em_2p+1, ep_2p, ep_2p+1)
//    thread c reads pairs {c, c+8, c+16, c+24}: conflict-free LDS.128
//  - bl smem: 3 pre-duplicated u64 planes [KC][BM]; row-pair LDS.128 broadcast
// ---------------------------------------------------------------------------
__global__ void __launch_bounds__(NTHR, 5)
main_kernel(float* __restrict__ out,
            const float* __restrict__ vp,
            const float* __restrict__ bptr) {
    extern __shared__ char sm[];
    float4* s_v  = (float4*)sm;                       // [NK][32] pairs   32KB
    u64*    s_cp = (u64*)(sm + NK * 32 * 16);         // [KC][BM]          4KB
    u64*    s_ep = s_cp + KC * BM;                    //                   4KB
    u64*    s_em = s_ep + KC * BM;                    //                   4KB

    const int tid    = threadIdx.x;
    const int vbase  = blockIdx.x * BN;
    const int blbase = blockIdx.y * BM;

    // --- In-kernel vocab exp fill: 2048 (k, pair) items, 16 per thread ---
    #pragma unroll
    for (int it = 0; it < 16; ++it) {
        int idx = it * NTHR + tid;          // lanes sweep k -> coalesced LDG
        int p = idx >> 6;                   // 0..31
        int k = idx & 63;
        long a = (long)(vbase + 2 * p) * NK + k;
        float x0 = vp[a];
        float x1 = vp[a + NK];
        s_v[k * 32 + p] = make_float4(__expf(-x0), __expf(-x1),
                                      __expf(x0),  __expf(x1));
    }

    const int c  = tid & 7;                 // vocab pair group
    const int r0 = (tid >> 3) * 4;          // first of 4 bl rows

    u64 acc[4][4];
    #pragma unroll
    for (int i = 0; i < 4; ++i)
        #pragma unroll
        for (int j = 0; j < 4; ++j) acc[i][j] = 0ull;

    for (int kc = 0; kc < NK; kc += KC) {
        // --- bl chunk fill: 3 planes x 256 ulonglong2, coalesced ---
        #pragma unroll
        for (int it = 0; it < 2; ++it) {
            int idx = it * NTHR + tid;              // 0..255
            int kl = idx >> 5, pb = idx & 31;
            long src = (((long)(kc + kl) * NBL + blbase) >> 1) + pb;
            int  dst = kl * (BM / 2) + pb;
            ((ulonglong2*)s_cp)[dst] = ((const ulonglong2*)g_cpd)[src];
            ((ulonglong2*)s_ep)[dst] = ((const ulonglong2*)g_epd)[src];
            ((ulonglong2*)s_em)[dst] = ((const ulonglong2*)g_emd)[src];
        }
        __syncthreads();   // also covers the vocab fill on the first chunk

        #pragma unroll
        for (int kl = 0; kl < KC; ++kl) {
            const ulonglong2* vv = (const ulonglong2*)s_v + (kc + kl) * 32 + c;
            ulonglong2 q0 = vv[0];     // .x=(em,em') .y=(ep,ep')
            ulonglong2 q1 = vv[8];
            ulonglong2 q2 = vv[16];
            ulonglong2 q3 = vv[24];

            const u64* pc = s_cp + kl * BM + r0;
            const u64* pe = s_ep + kl * BM + r0;
            const u64* pm = s_em + kl * BM + r0;

            #pragma unroll
            for (int rp = 0; rp < 2; ++rp) {        // row pairs
                ulonglong2 cc = *(const ulonglong2*)(pc + 2 * rp);
                ulonglong2 ee = *(const ulonglong2*)(pe + 2 * rp);
                ulonglong2 mm = *(const ulonglong2*)(pm + 2 * rp);

                #pragma unroll
                for (int j = 0; j < 4; ++j) {
                    ulonglong2 q = (j == 0) ? q0 : (j == 1) ? q1 : (j == 2) ? q2 : q3;
                    {
                        u64 t1 = mul2(ee.x, q.x), t2 = mul2(mm.x, q.y);
                        float a0, a1, b0, b1; upk(t1, a0, a1); upk(t2, b0, b1);
                        acc[2*rp][j]   = fma2(cc.x, pk(fminf(a0, b0), fminf(a1, b1)), acc[2*rp][j]);
                    }
                    {
                        u64 t1 = mul2(ee.y, q.x), t2 = mul2(mm.y, q.y);
                        float a0, a1, b0, b1; upk(t1, a0, a1); upk(t2, b0, b1);
                        acc[2*rp+1][j] = fma2(cc.y, pk(fminf(a0, b0), fminf(a1, b1)), acc[2*rp+1][j]);
                    }
                }
            }
        }
        __syncthreads();
    }

    // --- Epilogue: 4 rows x 4 pair-stores (STG.64, contiguous per quarter) ---
    const float bias = bptr[0];
    const u64 bias2 = pk(bias, bias);
    #pragma unroll
    for (int i = 0; i < 4; ++i) {
        long rowbase = (long)(blbase + r0 + i) * VOCAB + vbase + 2 * c;
        #pragma unroll
        for (int j = 0; j < 4; ++j) {
            *(u64*)&out[rowbase + 16 * j] = add2(acc[i][j], bias2);
        }
    }
}

// ---------------------------------------------------------------------------
extern "C" void kernel_launch(void* const* d_in, const int* in_sizes, int n_in,
                              void* d_out, int out_size) {
    const float* freqs  = (const float*)d_in[0];
    const float* amps   = (const float*)d_in[1];
    const float* phases = (const float*)d_in[2];
    const float* vp     = (const float*)d_in[3];
    const float* iph    = (const float*)d_in[4];
    const float* W      = (const float*)d_in[5];
    const float* b      = (const float*)d_in[6];
    float* out = (float*)d_out;

    prep_bl<<<(NBL * NK) / 256, 256>>>(freqs, amps, phases, iph, W);

    const int smem_bytes = NK * 32 * 16 + 3 * KC * BM * (int)sizeof(u64);  // 45056
    cudaFuncSetAttribute(main_kernel, cudaFuncAttributeMaxDynamicSharedMemorySize, smem_bytes);
    cudaFuncSetAttribute(main_kernel, cudaFuncAttributePreferredSharedMemoryCarveout, 100);

    dim3 grid(VOCAB / BN, NBL / BM);   // (500, 2)
    main_kernel<<<grid, NTHR, smem_bytes>>>(out, vp, b);
    (void)in_sizes; (void)n_in; (void)out_size;
}

// round 7
// speedup vs baseline: 1.1137x; 1.1137x over previous
#include <cuda_runtime.h>
#include <math.h>

// Problem constants (fixed by the dataset)
#define VOCAB   32000
#define NBL     128        // B*L
#define NK      64         // 8 heads x 8

// Main-kernel tiling: 256 threads, each owns 4 bl-rows x 8 vocab-cols
#define BM      128        // full bl dimension per CTA
#define BN      64         // vocab tile -> grid.x = 500
#define KC      16         // k chunk for bl-coefficient smem
#define NTHR    256

typedef unsigned long long u64;

// ---------------------------------------------------------------------------
// Packed f32x2 helpers
// ---------------------------------------------------------------------------
__device__ __forceinline__ u64 pk(float x, float y) {
    u64 r; asm("mov.b64 %0, {%1, %2};" : "=l"(r) : "f"(x), "f"(y)); return r;
}
__device__ __forceinline__ void upk(u64 a, float& x, float& y) {
    asm("mov.b64 {%0, %1}, %2;" : "=f"(x), "=f"(y) : "l"(a));
}
__device__ __forceinline__ u64 mul2(u64 a, u64 b) {
    u64 r; asm("mul.rn.f32x2 %0, %1, %2;" : "=l"(r) : "l"(a), "l"(b)); return r;
}
__device__ __forceinline__ u64 fma2(u64 a, u64 b, u64 c) {
    u64 r; asm("fma.rn.f32x2 %0, %1, %2, %3;" : "=l"(r) : "l"(a), "l"(b), "l"(c)); return r;
}

// ---------------------------------------------------------------------------
// Device scratch: per-(k,bl) scalar coefficient planes
// ---------------------------------------------------------------------------
__device__ __align__(16) float g_cp[NK * NBL];   // [k][bl] = W[h]*a*cos(p - iph)
__device__ __align__(16) float g_ep[NK * NBL];   // [k][bl] = e^freq
__device__ __align__(16) float g_em[NK * NBL];   // [k][bl] = e^-freq

__global__ void prep_bl(const float* __restrict__ freqs,
                        const float* __restrict__ amps,
                        const float* __restrict__ phases,
                        const float* __restrict__ iph,
                        const float* __restrict__ W) {
    int idx = blockIdx.x * 256 + threadIdx.x;   // idx = bl*NK + k
    int bl = idx >> 6, k = idx & 63;
    float cp = amps[idx] * cosf(phases[idx] - iph[k]) * W[k >> 3];
    float f  = freqs[idx];
    int o = k * NBL + bl;
    g_cp[o] = cp;
    g_ep[o] = expf(f);
    g_em[o] = expf(-f);
}

// ---------------------------------------------------------------------------
// Main: out[bl][v] = sum_k cp * min(e^f * e^-vp, e^-f * e^vp) + bias
//  - vocab smem: [k][pair p] float4 = (em_2p, em_2p+1, ep_2p, ep_2p+1)
//    thread c reads pairs {c, c+8, c+16, c+24}: conflict-free LDS.128
//  - bl smem: 3 scalar planes [KC][BM]; one broadcast LDS.128 per plane/kl
// ---------------------------------------------------------------------------
__global__ void __launch_bounds__(NTHR, 3)
main_kernel(float* __restrict__ out,
            const float* __restrict__ vp,
            const float* __restrict__ bptr) {
    extern __shared__ char sm[];
    float4* s_v  = (float4*)sm;                   // [NK][32] pairs   32KB
    float*  s_cp = (float*)(sm + NK * 32 * 16);   // [KC][BM]          8KB
    float*  s_ep = s_cp + KC * BM;                //                   8KB
    float*  s_em = s_ep + KC * BM;                //                   8KB

    const int tid   = threadIdx.x;
    const int vbase = blockIdx.x * BN;

    // --- In-kernel vocab exp fill: 2048 (pair,k) items, 8 per thread ---
    #pragma unroll
    for (int it = 0; it < 8; ++it) {
        int idx = it * NTHR + tid;          // lanes sweep k -> coalesced LDG
        int p = idx >> 6;                   // 0..31
        int k = idx & 63;
        long a = (long)(vbase + 2 * p) * NK + k;
        float x0 = vp[a];
        float x1 = vp[a + NK];
        s_v[k * 32 + p] = make_float4(__expf(-x0), __expf(-x1),
                                      __expf(x0),  __expf(x1));
    }

    const int c  = tid & 7;                 // vocab pair group
    const int r4 = tid >> 3;                // bl row-group (float4 index), rows 4*r4..4*r4+3

    const float bias = bptr[0];
    const u64 bias2 = pk(bias, bias);
    u64 acc[4][4];
    #pragma unroll
    for (int i = 0; i < 4; ++i)
        #pragma unroll
        for (int j = 0; j < 4; ++j) acc[i][j] = bias2;   // bias folded into init

    for (int kc = 0; kc < NK; kc += KC) {
        // --- bl chunk fill: 3 planes x 512 float4, coalesced ---
        const float4* gc = (const float4*)(g_cp + kc * NBL);
        const float4* ge = (const float4*)(g_ep + kc * NBL);
        const float4* gm = (const float4*)(g_em + kc * NBL);
        #pragma unroll
        for (int it = 0; it < (KC * BM / 4) / NTHR; ++it) {   // 2 iters
            int idx = it * NTHR + tid;
            ((float4*)s_cp)[idx] = gc[idx];
            ((float4*)s_ep)[idx] = ge[idx];
            ((float4*)s_em)[idx] = gm[idx];
        }
        __syncthreads();   // also covers the vocab fill on the first chunk

        #pragma unroll
        for (int kl = 0; kl < KC; ++kl) {
            const ulonglong2* vv = (const ulonglong2*)s_v + (kc + kl) * 32 + c;
            ulonglong2 q0 = vv[0];     // .x=(em,em') .y=(ep,ep')
            ulonglong2 q1 = vv[8];
            ulonglong2 q2 = vv[16];
            ulonglong2 q3 = vv[24];

            // one broadcast LDS.128 per plane -> this thread's 4 rows
            float4 vc = ((const float4*)(s_cp + kl * BM))[r4];
            float4 veq = ((const float4*)(s_ep + kl * BM))[r4];
            float4 vmq = ((const float4*)(s_em + kl * BM))[r4];
            const float* vcf = (const float*)&vc;
            const float* vef = (const float*)&veq;
            const float* vmf = (const float*)&vmq;

            #pragma unroll
            for (int i = 0; i < 4; ++i) {
                float cs = vcf[i], es = vef[i], ms = vmf[i];
                u64 cpd = pk(cs, cs);
                u64 epd = pk(es, es);
                u64 emd = pk(ms, ms);
                {
                    u64 t1 = mul2(epd, q0.x), t2 = mul2(emd, q0.y);
                    float a0, a1, b0, b1; upk(t1, a0, a1); upk(t2, b0, b1);
                    acc[i][0] = fma2(cpd, pk(fminf(a0, b0), fminf(a1, b1)), acc[i][0]);
                }
                {
                    u64 t1 = mul2(epd, q1.x), t2 = mul2(emd, q1.y);
                    float a0, a1, b0, b1; upk(t1, a0, a1); upk(t2, b0, b1);
                    acc[i][1] = fma2(cpd, pk(fminf(a0, b0), fminf(a1, b1)), acc[i][1]);
                }
                {
                    u64 t1 = mul2(epd, q2.x), t2 = mul2(emd, q2.y);
                    float a0, a1, b0, b1; upk(t1, a0, a1); upk(t2, b0, b1);
                    acc[i][2] = fma2(cpd, pk(fminf(a0, b0), fminf(a1, b1)), acc[i][2]);
                }
                {
                    u64 t1 = mul2(epd, q3.x), t2 = mul2(emd, q3.y);
                    float a0, a1, b0, b1; upk(t1, a0, a1); upk(t2, b0, b1);
                    acc[i][3] = fma2(cpd, pk(fminf(a0, b0), fminf(a1, b1)), acc[i][3]);
                }
            }
        }
        __syncthreads();
    }

    // --- Epilogue: 4 rows x 4 u64 pair-stores each (bias already in acc) ---
    #pragma unroll
    for (int i = 0; i < 4; ++i) {
        long rowbase = (long)(4 * r4 + i) * VOCAB + vbase + 2 * c;
        #pragma unroll
        for (int j = 0; j < 4; ++j) {
            *(u64*)&out[rowbase + 16 * j] = acc[i][j];
        }
    }
}

// ---------------------------------------------------------------------------
extern "C" void kernel_launch(void* const* d_in, const int* in_sizes, int n_in,
                              void* d_out, int out_size) {
    const float* freqs  = (const float*)d_in[0];
    const float* amps   = (const float*)d_in[1];
    const float* phases = (const float*)d_in[2];
    const float* vp     = (const float*)d_in[3];
    const float* iph    = (const float*)d_in[4];
    const float* W      = (const float*)d_in[5];
    const float* b      = (const float*)d_in[6];
    float* out = (float*)d_out;

    prep_bl<<<(NBL * NK) / 256, 256>>>(freqs, amps, phases, iph, W);

    const int smem_bytes = NK * 32 * 16 + 3 * KC * BM * (int)sizeof(float);  // 57344
    cudaFuncSetAttribute(main_kernel, cudaFuncAttributeMaxDynamicSharedMemorySize, smem_bytes);
    cudaFuncSetAttribute(main_kernel, cudaFuncAttributePreferredSharedMemoryCarveout, 100);

    main_kernel<<<VOCAB / BN, NTHR, smem_bytes>>>(out, vp, b);
    (void)in_sizes; (void)n_in; (void)out_size;
}